// round 6
// baseline (speedup 1.0000x reference)
#include <cuda_runtime.h>
#include <cuda_bf16.h>
#include <cstdint>

#define T_LEN 64000
#define NB 4
#define CH 128
#define NCLS 256
// layer kernel tiling
#define LCH 64               // t per chunk
#define LNCH 4               // chunks per CTA
#define SPAN 256             // t per CTA
#define NXCTA (T_LEN / SPAN) // 250
// classifier tiling (unchanged)
#define CCH 32
#define CNCH 8

// ---------------- static device buffers ----------------
__device__ unsigned short g_act0[(size_t)NB * 2 * T_LEN * CH];
__device__ unsigned short g_act1[(size_t)NB * 2 * T_LEN * CH];
__device__ uint32_t g_whi[27 * 2 * 128 * 64];
__device__ uint32_t g_wlo[27 * 2 * 128 * 64];
__device__ uint32_t g_wc[2 * 256 * 64];

// ---------------- helpers ----------------
__device__ __forceinline__ uint32_t smem_u32(const void* p) {
    uint32_t a;
    asm("{ .reg .u64 t; cvta.to.shared.u64 t, %1; cvt.u32.u64 %0, t; }" : "=r"(a) : "l"(p));
    return a;
}
__device__ __forceinline__ void cpa16(uint32_t dst, const void* src, int sz) {
    asm volatile("cp.async.cg.shared.global [%0], [%1], 16, %2;"
                 :: "r"(dst), "l"(src), "r"(sz) : "memory");
}
#define CP_COMMIT() asm volatile("cp.async.commit_group;" ::: "memory")
#define CP_WAIT1()  asm volatile("cp.async.wait_group 1;" ::: "memory")
#define CP_WAIT0()  asm volatile("cp.async.wait_group 0;" ::: "memory")

__device__ __forceinline__ void mma16816(float c[4], const uint32_t a[4],
                                         uint32_t b0, uint32_t b1) {
    asm volatile(
        "mma.sync.aligned.m16n8k16.row.col.f32.bf16.bf16.f32 "
        "{%0,%1,%2,%3}, {%4,%5,%6,%7}, {%8,%9}, {%0,%1,%2,%3};"
        : "+f"(c[0]), "+f"(c[1]), "+f"(c[2]), "+f"(c[3])
        : "r"(a[0]), "r"(a[1]), "r"(a[2]), "r"(a[3]), "r"(b0), "r"(b1));
}

// ---------------- prep: split + pack weights ----------------
__device__ __forceinline__ uint32_t pack_split(float w0, float w1, int plane) {
    __nv_bfloat16 h0 = __float2bfloat16(w0), h1 = __float2bfloat16(w1);
    if (plane == 0)
        return (uint32_t)__bfloat16_as_ushort(h0) |
               ((uint32_t)__bfloat16_as_ushort(h1) << 16);
    __nv_bfloat16 l0 = __float2bfloat16(w0 - __bfloat162float(h0));
    __nv_bfloat16 l1 = __float2bfloat16(w1 - __bfloat162float(h1));
    return (uint32_t)__bfloat16_as_ushort(l0) |
           ((uint32_t)__bfloat16_as_ushort(l1) << 16);
}

__global__ void prep_kernel(const float* __restrict__ wrest,
                            const float* __restrict__ wcls,
                            uint32_t* __restrict__ whi,
                            uint32_t* __restrict__ wlo,
                            uint32_t* __restrict__ wc) {
    int idx = blockIdx.x * blockDim.x + threadIdx.x;
    if (idx < 27 * 2 * 128 * 64) {
        int kp = idx & 63;
        int m = (idx >> 6) & 127;
        int tap = (idx >> 13) & 1;
        int L = idx >> 14;
        float w0 = wrest[((L * 128 + m) * 128 + kp * 2) * 2 + tap];
        float w1 = wrest[((L * 128 + m) * 128 + kp * 2 + 1) * 2 + tap];
        whi[idx] = pack_split(w0, w1, 0);
        wlo[idx] = pack_split(w0, w1, 1);
    }
    if (idx < 2 * 256 * 64) {
        int kp = idx & 63;
        int m = (idx >> 6) & 255;
        int pl = idx >> 14;
        float w0 = wcls[m * 128 + kp * 2];
        float w1 = wcls[m * 128 + kp * 2 + 1];
        wc[idx] = pack_split(w0, w1, pl);
    }
}

// ---------------- layer 0 ----------------
__global__ void layer0_kernel(const float* __restrict__ seq,
                              const float* __restrict__ wf,
                              unsigned short* __restrict__ actout) {
    int oc = threadIdx.x & 127;
    int half = threadIdx.x >> 7;
    int n = blockIdx.y;
    int t0 = blockIdx.x * 128 + half * 64;
    float w0 = wf[oc * 2], w1 = wf[oc * 2 + 1];
    const float* xs = seq + (size_t)n * T_LEN;
    unsigned short* ohi = actout + (size_t)(n * 2 + 0) * T_LEN * CH;
    unsigned short* olo = actout + (size_t)(n * 2 + 1) * T_LEN * CH;
    for (int j = 0; j < 64; j++) {
        int t = t0 + j;
        float x1 = xs[t];
        float x0 = (t >= 1) ? xs[t - 1] : 0.f;
        float y = fmaxf(w0 * x0 + w1 * x1, 0.f);
        __nv_bfloat16 h = __float2bfloat16(y);
        __nv_bfloat16 l = __float2bfloat16(y - __bfloat162float(h));
        ohi[(size_t)t * CH + oc] = __bfloat16_as_ushort(h);
        olo[(size_t)t * CH + oc] = __bfloat16_as_ushort(l);
    }
}

// ---------------- dilated-conv layer via mma.sync bf16 ----------------
// smem (u32 units):
//   [0, 17408)        Wl: [tap][m 128][68]
//   [17408, 52224)    X : [buf 2][tile 4 = tap*2+plane][r 64][68]
//   [52224, 56576)    stage: u16[2 pl][32 t][136 m]
// CTA tile per chunk: 128 oc x 64 t. 8 warps = 4(m) x 2(n of 32 each).
__global__ void __launch_bounds__(256, 1) layer_mma(
    const unsigned short* __restrict__ actin,
    unsigned short* __restrict__ actout,
    const uint32_t* __restrict__ whi,
    const uint32_t* __restrict__ wlo, int d) {
    extern __shared__ uint32_t sm[];
    const uint32_t sb = smem_u32(sm);
    const int tid = threadIdx.x;
    const int lane = tid & 31, wid = tid >> 5;
    const int g = lane >> 2, tq = lane & 3;
    const int n = blockIdx.y;
    const int tbase = blockIdx.x * SPAN;
    const int m0 = (wid & 3) * 32;
    const int n0 = (wid >> 2) * 32;

    // ---- group 0: Wl -> smem
#pragma unroll
    for (int i = 0; i < 16; i++) {
        int idx = i * 256 + tid;
        int row = idx >> 4, seg = idx & 15;
        cpa16(sb + (row * 68 + seg * 4) * 4, wlo + row * 64 + seg * 4, 16);
    }
    CP_COMMIT();

    auto load_x = [&](int c) {
        int buf = c & 1;
        int tcb = tbase + c * LCH;
#pragma unroll
        for (int i = 0; i < 16; i++) {
            int idx = i * 256 + tid;       // 4096 segs
            int tile = idx >> 10, rem = idx & 1023;
            int r = rem >> 4, seg = rem & 15;
            int tap = tile >> 1, pl = tile & 1;
            int t = tcb + r - (tap == 0 ? d : 0);
            const unsigned short* src =
                actin + ((size_t)(n * 2 + pl) * T_LEN + (t < 0 ? 0 : t)) * CH + seg * 8;
            cpa16(sb + (17408 + buf * 17408 + tile * 4352 + r * 68 + seg * 4) * 4,
                  src, t >= 0 ? 16 : 0);
        }
        CP_COMMIT();
    };
    load_x(0);
    load_x(1);

    // ---- preload Wh fragments into registers (chunk-invariant)
    uint32_t wh[2][8][2][4];
#pragma unroll
    for (int tap = 0; tap < 2; tap++)
#pragma unroll
        for (int ks = 0; ks < 8; ks++)
#pragma unroll
            for (int mt = 0; mt < 2; mt++) {
                const uint32_t* wp = whi + (tap * 128 + m0 + mt * 16) * 64;
                wh[tap][ks][mt][0] = wp[(g)*64 + ks * 8 + tq];
                wh[tap][ks][mt][1] = wp[(g + 8) * 64 + ks * 8 + tq];
                wh[tap][ks][mt][2] = wp[(g)*64 + ks * 8 + 4 + tq];
                wh[tap][ks][mt][3] = wp[(g + 8) * 64 + ks * 8 + 4 + tq];
            }

    CP_WAIT1();          // Wl + chunk0 complete (chunk1 in flight)
    __syncthreads();

    unsigned short* stg = (unsigned short*)(sm + 52224);

#pragma unroll 1
    for (int c = 0; c < LNCH; c++) {
        const int buf = c & 1;
        const uint32_t* X = sm + 17408 + buf * 17408;

        float acc[2][4][4];
#pragma unroll
        for (int mt = 0; mt < 2; mt++)
#pragma unroll
            for (int nt = 0; nt < 4; nt++)
#pragma unroll
                for (int j = 0; j < 4; j++) acc[mt][nt][j] = 0.f;

        // -- passes 1,2: Wh (regs) x {Xh, Xl}
#pragma unroll
        for (int xpl = 0; xpl < 2; xpl++)
#pragma unroll
            for (int tap = 0; tap < 2; tap++) {
                const uint32_t* Xt = X + (tap * 2 + xpl) * 4352;
#pragma unroll
                for (int ks = 0; ks < 8; ks++) {
                    uint32_t b0[4], b1[4];
#pragma unroll
                    for (int nt = 0; nt < 4; nt++) {
                        const uint32_t* xr = Xt + (n0 + nt * 8 + g) * 68;
                        b0[nt] = xr[ks * 8 + tq];
                        b1[nt] = xr[ks * 8 + 4 + tq];
                    }
#pragma unroll
                    for (int mt = 0; mt < 2; mt++)
#pragma unroll
                        for (int nt = 0; nt < 4; nt++)
                            mma16816(acc[mt][nt], wh[tap][ks][mt], b0[nt], b1[nt]);
                }
            }

        // -- pass 3: Wl (smem) x Xh
#pragma unroll
        for (int tap = 0; tap < 2; tap++) {
            const uint32_t* Xt = X + (tap * 2 + 0) * 4352;
            const uint32_t* Wt = sm + tap * 8704;
#pragma unroll
            for (int ks = 0; ks < 8; ks++) {
                uint32_t a[2][4], b0[4], b1[4];
#pragma unroll
                for (int mt = 0; mt < 2; mt++) {
                    a[mt][0] = Wt[(m0 + mt * 16 + g) * 68 + ks * 8 + tq];
                    a[mt][1] = Wt[(m0 + mt * 16 + g + 8) * 68 + ks * 8 + tq];
                    a[mt][2] = Wt[(m0 + mt * 16 + g) * 68 + ks * 8 + 4 + tq];
                    a[mt][3] = Wt[(m0 + mt * 16 + g + 8) * 68 + ks * 8 + 4 + tq];
                }
#pragma unroll
                for (int nt = 0; nt < 4; nt++) {
                    const uint32_t* xr = Xt + (n0 + nt * 8 + g) * 68;
                    b0[nt] = xr[ks * 8 + tq];
                    b1[nt] = xr[ks * 8 + 4 + tq];
                }
#pragma unroll
                for (int mt = 0; mt < 2; mt++)
#pragma unroll
                    for (int nt = 0; nt < 4; nt++)
                        mma16816(acc[mt][nt], a[mt], b0[nt], b1[nt]);
            }
        }

        __syncthreads();  // X[buf] reads done; prev-chunk stage reads done

        if (c + 2 < LNCH) load_x(c + 2);   // overlaps epilogue + next MMA

        const int tcb = tbase + c * LCH;
        // -- epilogue in two 32-t waves through the dedicated stage
#pragma unroll
        for (int h = 0; h < 2; h++) {
            if (n0 == h * 32) {
#pragma unroll
                for (int mt = 0; mt < 2; mt++)
#pragma unroll
                    for (int nt = 0; nt < 4; nt++)
#pragma unroll
                        for (int ci = 0; ci < 4; ci++) {
                            int m = m0 + mt * 16 + g + ((ci >> 1) * 8);
                            int tl = nt * 8 + tq * 2 + (ci & 1);   // 0..31 local
                            float y = fmaxf(acc[mt][nt][ci], 0.f);
                            __nv_bfloat16 hh = __float2bfloat16(y);
                            __nv_bfloat16 ll = __float2bfloat16(y - __bfloat162float(hh));
                            stg[tl * 136 + m] = __bfloat16_as_ushort(hh);
                            stg[4352 + tl * 136 + m] = __bfloat16_as_ushort(ll);
                        }
            }
            if (h == 1 && c + 1 < LNCH) {
                if (c + 2 < LNCH) CP_WAIT1();
                else CP_WAIT0();
            }
            __syncthreads();   // stage visible (+ next chunk data on h==1)
#pragma unroll
            for (int i = 0; i < 4; i++) {
                int idx = i * 256 + tid;    // 1024 uint4 per wave
                int pl = idx >> 9, rem = idx & 511;
                int r = rem >> 4, sg = rem & 15;
                uint4 v = *(const uint4*)(stg + pl * 4352 + r * 136 + sg * 8);
                *(uint4*)(actout + ((size_t)(n * 2 + pl) * T_LEN + tcb + h * 32 + r) * CH +
                          sg * 8) = v;
            }
            if (h == 0) __syncthreads();  // wave-0 stores read stage before wave-1 rewrites
        }
    }
}

// ---------------- classifier: 128 -> 256, + bias, no relu ----------------
// smem (u32): [0,17408) WC [pl][128][68]; [17408,26112) X [buf2][pl2][32][68];
//             [26112,30464) stage f32 [128][34]
__global__ void __launch_bounds__(256, 1) cls_mma(
    const unsigned short* __restrict__ actin,
    const uint32_t* __restrict__ wc,
    const float* __restrict__ bias,
    float* __restrict__ out) {
    extern __shared__ uint32_t sm[];
    const uint32_t sb = smem_u32(sm);
    const int tid = threadIdx.x;
    const int lane = tid & 31, wid = tid >> 5;
    const int g = lane >> 2, tq = lane & 3;
    const int n = blockIdx.y;
    const int tbase = blockIdx.x * SPAN;
    const int mz = blockIdx.z * 128;
    const int m0 = (wid & 3) * 32;
    const int n0 = (wid >> 2) * 16;

#pragma unroll
    for (int i = 0; i < 16; i++) {
        int idx = i * 256 + tid;
        int row = idx >> 4, seg = idx & 15;
        const uint32_t* src = wc + ((size_t)(row >> 7) * 256 + mz + (row & 127)) * 64 + seg * 4;
        cpa16(sb + (row * 68 + seg * 4) * 4, src, 16);
    }
    CP_COMMIT();

    auto load_x = [&](int c) {
        int buf = c & 1;
        int tcb = tbase + c * CCH;
#pragma unroll
        for (int i = 0; i < 4; i++) {
            int idx = i * 256 + tid;
            int pl = idx >> 9, rem = idx & 511;
            int r = rem >> 4, seg = rem & 15;
            const unsigned short* src =
                actin + ((size_t)(n * 2 + pl) * T_LEN + tcb + r) * CH + seg * 8;
            cpa16(sb + (17408 + buf * 4352 + pl * 2176 + r * 68 + seg * 4) * 4, src, 16);
        }
        CP_COMMIT();
    };
    load_x(0);
    load_x(1);
    CP_WAIT1();
    __syncthreads();

    float* stg = (float*)(sm + 26112);

#pragma unroll 1
    for (int c = 0; c < CNCH; c++) {
        const int buf = c & 1;
        const uint32_t* X = sm + 17408 + buf * 4352;

        float acc[2][2][4];
#pragma unroll
        for (int mt = 0; mt < 2; mt++)
#pragma unroll
            for (int nt = 0; nt < 2; nt++)
#pragma unroll
                for (int j = 0; j < 4; j++) acc[mt][nt][j] = 0.f;

#pragma unroll
        for (int pass = 0; pass < 3; pass++) {
            const int wp = (pass == 2) ? 1 : 0;
            const int xp = (pass == 1) ? 1 : 0;
            const uint32_t* Wt = sm + wp * 8704;
            const uint32_t* Xt = X + xp * 2176;
#pragma unroll
            for (int ks = 0; ks < 8; ks++) {
                uint32_t a[2][4], b0[2], b1[2];
#pragma unroll
                for (int mt = 0; mt < 2; mt++) {
                    a[mt][0] = Wt[(m0 + mt * 16 + g) * 68 + ks * 8 + tq];
                    a[mt][1] = Wt[(m0 + mt * 16 + g + 8) * 68 + ks * 8 + tq];
                    a[mt][2] = Wt[(m0 + mt * 16 + g) * 68 + ks * 8 + 4 + tq];
                    a[mt][3] = Wt[(m0 + mt * 16 + g + 8) * 68 + ks * 8 + 4 + tq];
                }
#pragma unroll
                for (int nt = 0; nt < 2; nt++) {
                    const uint32_t* xr = Xt + (n0 + nt * 8 + g) * 68;
                    b0[nt] = xr[ks * 8 + tq];
                    b1[nt] = xr[ks * 8 + 4 + tq];
                }
#pragma unroll
                for (int mt = 0; mt < 2; mt++)
#pragma unroll
                    for (int nt = 0; nt < 2; nt++)
                        mma16816(acc[mt][nt], a[mt], b0[nt], b1[nt]);
            }
        }

        __syncthreads();
        if (c + 2 < CNCH) load_x(c + 2);

#pragma unroll
        for (int mt = 0; mt < 2; mt++)
#pragma unroll
            for (int nt = 0; nt < 2; nt++)
#pragma unroll
                for (int ci = 0; ci < 4; ci++) {
                    int m = m0 + mt * 16 + g + ((ci >> 1) * 8);
                    int tl = n0 + nt * 8 + tq * 2 + (ci & 1);
                    stg[m * 34 + tl] = acc[mt][nt][ci] + __ldg(bias + mz + m);
                }

        if (c + 1 < CNCH) {
            if (c + 2 < CNCH) CP_WAIT1();
            else CP_WAIT0();
        }
        __syncthreads();

        const int tcb = tbase + c * CCH;
#pragma unroll
        for (int i = 0; i < 8; i++) {
            int idx = i * 256 + tid;
            int row = idx >> 4, sg = idx & 15;
            float2 v = *(const float2*)(stg + row * 34 + sg * 2);
            *(float2*)(out + ((size_t)n * NCLS + mz + row) * T_LEN + tcb + sg * 2) = v;
        }
    }
}

// ---------------- launch ----------------
extern "C" void kernel_launch(void* const* d_in, const int* in_sizes, int n_in,
                              void* d_out, int out_size) {
    (void)in_sizes; (void)n_in; (void)out_size;
    const float* seq     = (const float*)d_in[0];
    const float* w_first = (const float*)d_in[1];
    const float* w_rest  = (const float*)d_in[2];
    const float* w_cls   = (const float*)d_in[3];
    const float* b_cls   = (const float*)d_in[4];
    float* out = (float*)d_out;

    unsigned short *a0, *a1;
    uint32_t *whi, *wlo, *wc;
    cudaGetSymbolAddress((void**)&a0, g_act0);
    cudaGetSymbolAddress((void**)&a1, g_act1);
    cudaGetSymbolAddress((void**)&whi, g_whi);
    cudaGetSymbolAddress((void**)&wlo, g_wlo);
    cudaGetSymbolAddress((void**)&wc, g_wc);

    const int smem_layer = 56576 * 4;  // 226304 B
    const int smem_cls   = 30464 * 4;  // 121856 B
    cudaFuncSetAttribute(layer_mma, cudaFuncAttributeMaxDynamicSharedMemorySize, smem_layer);
    cudaFuncSetAttribute(cls_mma, cudaFuncAttributeMaxDynamicSharedMemorySize, smem_cls);

    prep_kernel<<<(27 * 2 * 128 * 64 + 255) / 256, 256>>>(w_rest, w_cls, whi, wlo, wc);
    layer0_kernel<<<dim3(T_LEN / 128, NB), 256>>>(seq, w_first, a0);

    for (int i = 1; i < 28; i++) {
        int l = i % 14;
        int d = 1 << (l % 10);
        const unsigned short* src = (i & 1) ? a0 : a1;
        unsigned short* dst       = (i & 1) ? a1 : a0;
        layer_mma<<<dim3(NXCTA, NB), 256, smem_layer>>>(
            src, dst, whi + (size_t)(i - 1) * 2 * 128 * 64,
            wlo + (size_t)(i - 1) * 2 * 128 * 64, d);
    }

    cls_mma<<<dim3(NXCTA, NB, 2), 256, smem_cls>>>(a1, wc, b_cls, out);
}

// round 7
// speedup vs baseline: 1.1461x; 1.1461x over previous
#include <cuda_runtime.h>
#include <cuda_bf16.h>
#include <cstdint>

#define T_LEN 64000
#define NB 4
#define CH 128
#define NCLS 256
#define CHUNK 32
#define NCHUNK 8
#define SPAN (CHUNK * NCHUNK)      // 256 t per CTA
#define NXCTA (T_LEN / SPAN)       // 250

// ---------------- static device buffers ----------------
__device__ unsigned short g_act0[(size_t)NB * 2 * T_LEN * CH];
__device__ unsigned short g_act1[(size_t)NB * 2 * T_LEN * CH];
__device__ uint32_t g_whi[27 * 2 * 128 * 64];
__device__ uint32_t g_wlo[27 * 2 * 128 * 64];
__device__ uint32_t g_wc[2 * 256 * 64];

// ---------------- helpers ----------------
__device__ __forceinline__ uint32_t smem_u32(const void* p) {
    uint32_t a;
    asm("{ .reg .u64 t; cvta.to.shared.u64 t, %1; cvt.u32.u64 %0, t; }" : "=r"(a) : "l"(p));
    return a;
}
__device__ __forceinline__ void cpa16(uint32_t dst, const void* src, int sz) {
    asm volatile("cp.async.cg.shared.global [%0], [%1], 16, %2;"
                 :: "r"(dst), "l"(src), "r"(sz) : "memory");
}
#define CP_COMMIT() asm volatile("cp.async.commit_group;" ::: "memory")
#define CP_WAIT1()  asm volatile("cp.async.wait_group 1;" ::: "memory")
#define CP_WAIT0()  asm volatile("cp.async.wait_group 0;" ::: "memory")

__device__ __forceinline__ void mma16816(float c[4], const uint32_t a[4],
                                         uint32_t b0, uint32_t b1) {
    asm volatile(
        "mma.sync.aligned.m16n8k16.row.col.f32.bf16.bf16.f32 "
        "{%0,%1,%2,%3}, {%4,%5,%6,%7}, {%8,%9}, {%0,%1,%2,%3};"
        : "+f"(c[0]), "+f"(c[1]), "+f"(c[2]), "+f"(c[3])
        : "r"(a[0]), "r"(a[1]), "r"(a[2]), "r"(a[3]), "r"(b0), "r"(b1));
}

// ---------------- prep: split + pack weights ----------------
__device__ __forceinline__ uint32_t pack_split(float w0, float w1, int plane) {
    __nv_bfloat16 h0 = __float2bfloat16(w0), h1 = __float2bfloat16(w1);
    if (plane == 0)
        return (uint32_t)__bfloat16_as_ushort(h0) |
               ((uint32_t)__bfloat16_as_ushort(h1) << 16);
    __nv_bfloat16 l0 = __float2bfloat16(w0 - __bfloat162float(h0));
    __nv_bfloat16 l1 = __float2bfloat16(w1 - __bfloat162float(h1));
    return (uint32_t)__bfloat16_as_ushort(l0) |
           ((uint32_t)__bfloat16_as_ushort(l1) << 16);
}

__global__ void prep_kernel(const float* __restrict__ wrest,
                            const float* __restrict__ wcls,
                            uint32_t* __restrict__ whi,
                            uint32_t* __restrict__ wlo,
                            uint32_t* __restrict__ wc) {
    int idx = blockIdx.x * blockDim.x + threadIdx.x;
    if (idx < 27 * 2 * 128 * 64) {
        int kp = idx & 63;
        int m = (idx >> 6) & 127;
        int tap = (idx >> 13) & 1;
        int L = idx >> 14;
        float w0 = wrest[((L * 128 + m) * 128 + kp * 2) * 2 + tap];
        float w1 = wrest[((L * 128 + m) * 128 + kp * 2 + 1) * 2 + tap];
        whi[idx] = pack_split(w0, w1, 0);
        wlo[idx] = pack_split(w0, w1, 1);
    }
    if (idx < 2 * 256 * 64) {
        int kp = idx & 63;
        int m = (idx >> 6) & 255;
        int pl = idx >> 14;
        float w0 = wcls[m * 128 + kp * 2];
        float w1 = wcls[m * 128 + kp * 2 + 1];
        wc[idx] = pack_split(w0, w1, pl);
    }
}

// ---------------- layer 0 ----------------
__global__ void layer0_kernel(const float* __restrict__ seq,
                              const float* __restrict__ wf,
                              unsigned short* __restrict__ actout) {
    int oc = threadIdx.x & 127;
    int half = threadIdx.x >> 7;
    int n = blockIdx.y;
    int t0 = blockIdx.x * 128 + half * 64;
    float w0 = wf[oc * 2], w1 = wf[oc * 2 + 1];
    const float* xs = seq + (size_t)n * T_LEN;
    unsigned short* ohi = actout + (size_t)(n * 2 + 0) * T_LEN * CH;
    unsigned short* olo = actout + (size_t)(n * 2 + 1) * T_LEN * CH;
    for (int j = 0; j < 64; j++) {
        int t = t0 + j;
        float x1 = xs[t];
        float x0 = (t >= 1) ? xs[t - 1] : 0.f;
        float y = fmaxf(w0 * x0 + w1 * x1, 0.f);
        __nv_bfloat16 h = __float2bfloat16(y);
        __nv_bfloat16 l = __float2bfloat16(y - __bfloat162float(h));
        ohi[(size_t)t * CH + oc] = __bfloat16_as_ushort(h);
        olo[(size_t)t * CH + oc] = __bfloat16_as_ushort(l);
    }
}

// ---------------- dilated-conv layer via mma.sync bf16 ----------------
// smem (u32 units):
//   [0, 34816)        W : [pl 2][tap 2][m 128][68]
//   [34816, 52224)    X : [buf 2][tile 4 = tap*2+plane][r 32][68]
//   [52224, 56576)    stage: u16[2 pl][32 t][136 m]
// CTA tile per chunk: 128 oc x 32 t. 8 warps = 4(m) x 2(n).
__global__ void __launch_bounds__(256, 1) layer_mma(
    const unsigned short* __restrict__ actin,
    unsigned short* __restrict__ actout,
    const uint32_t* __restrict__ whi,
    const uint32_t* __restrict__ wlo, int d) {
    extern __shared__ uint32_t sm[];
    const uint32_t sb = smem_u32(sm);
    const int tid = threadIdx.x;
    const int lane = tid & 31, wid = tid >> 5;
    const int g = lane >> 2, tq = lane & 3;
    const int n = blockIdx.y;
    const int tbase = blockIdx.x * SPAN;
    const int m0 = (wid & 3) * 32;
    const int n0 = (wid >> 2) * 16;

    // ---- group 0: W (both planes) -> smem
#pragma unroll
    for (int i = 0; i < 32; i++) {
        int idx = i * 256 + tid;         // 8192 segs of 16B
        int row = idx >> 4, seg = idx & 15;   // row = pl*256 + tap*128 + m
        const uint32_t* src = ((row < 256) ? whi : wlo) + (row & 255) * 64 + seg * 4;
        cpa16(sb + (row * 68 + seg * 4) * 4, src, 16);
    }
    CP_COMMIT();

    auto load_x = [&](int c) {
        int buf = c & 1;
        int tcb = tbase + c * CHUNK;
#pragma unroll
        for (int i = 0; i < 8; i++) {
            int idx = i * 256 + tid;
            int tile = idx >> 9, rem = idx & 511;
            int r = rem >> 4, seg = rem & 15;
            int tap = tile >> 1, pl = tile & 1;
            int t = tcb + r - (tap == 0 ? d : 0);
            const unsigned short* src =
                actin + ((size_t)(n * 2 + pl) * T_LEN + (t < 0 ? 0 : t)) * CH + seg * 8;
            cpa16(sb + (34816 + buf * 8704 + tile * 2176 + r * 68 + seg * 4) * 4,
                  src, t >= 0 ? 16 : 0);
        }
        CP_COMMIT();
    };
    load_x(0);
    load_x(1);

    CP_WAIT1();          // W + chunk0 complete (chunk1 in flight)
    __syncthreads();

    unsigned short* stg = (unsigned short*)(sm + 52224);

#pragma unroll 1
    for (int c = 0; c < NCHUNK; c++) {
        const int buf = c & 1;
        const uint32_t* X = sm + 34816 + buf * 8704;

        float acc[2][2][4];
#pragma unroll
        for (int mt = 0; mt < 2; mt++)
#pragma unroll
            for (int nt = 0; nt < 2; nt++)
#pragma unroll
                for (int j = 0; j < 4; j++) acc[mt][nt][j] = 0.f;

        // 6 segments: (wpl, xpl, tap) = (0,0,0)(0,0,1)(0,1,0)(0,1,1)(1,0,0)(1,0,1)
#pragma unroll
        for (int sgi = 0; sgi < 6; sgi++) {
            const int wpl = (sgi >= 4) ? 1 : 0;
            const int xpl = (sgi == 2 || sgi == 3) ? 1 : 0;
            const int tap = sgi & 1;
            const uint32_t* Wt = sm + wpl * 17408 + tap * 8704;
            const uint32_t* Xt = X + (tap * 2 + xpl) * 2176;
#pragma unroll
            for (int ks = 0; ks < 8; ks++) {
                uint32_t a[2][4], b0[2], b1[2];
#pragma unroll
                for (int mt = 0; mt < 2; mt++) {
                    a[mt][0] = Wt[(m0 + mt * 16 + g) * 68 + ks * 8 + tq];
                    a[mt][1] = Wt[(m0 + mt * 16 + g + 8) * 68 + ks * 8 + tq];
                    a[mt][2] = Wt[(m0 + mt * 16 + g) * 68 + ks * 8 + 4 + tq];
                    a[mt][3] = Wt[(m0 + mt * 16 + g + 8) * 68 + ks * 8 + 4 + tq];
                }
#pragma unroll
                for (int nt = 0; nt < 2; nt++) {
                    const uint32_t* xr = Xt + (n0 + nt * 8 + g) * 68;
                    b0[nt] = xr[ks * 8 + tq];
                    b1[nt] = xr[ks * 8 + 4 + tq];
                }
#pragma unroll
                for (int mt = 0; mt < 2; mt++)
#pragma unroll
                    for (int nt = 0; nt < 2; nt++)
                        mma16816(acc[mt][nt], a[mt], b0[nt], b1[nt]);
            }
        }

        __syncthreads();  // X[buf] reads done by all warps; stage(prev) reads done

        if (c + 2 < NCHUNK) load_x(c + 2);  // overlaps epilogue + next chunk MMA

        // -- epilogue: relu + split into dedicated stage
#pragma unroll
        for (int mt = 0; mt < 2; mt++)
#pragma unroll
            for (int nt = 0; nt < 2; nt++)
#pragma unroll
                for (int ci = 0; ci < 4; ci++) {
                    int m = m0 + mt * 16 + g + ((ci >> 1) * 8);
                    int tl = n0 + nt * 8 + tq * 2 + (ci & 1);
                    float y = fmaxf(acc[mt][nt][ci], 0.f);
                    __nv_bfloat16 h = __float2bfloat16(y);
                    __nv_bfloat16 l = __float2bfloat16(y - __bfloat162float(h));
                    stg[tl * 136 + m] = __bfloat16_as_ushort(h);
                    stg[4352 + tl * 136 + m] = __bfloat16_as_ushort(l);
                }

        if (c + 1 < NCHUNK) {
            if (c + 2 < NCHUNK) CP_WAIT1();
            else CP_WAIT0();
        }
        __syncthreads();  // stage visible + chunk c+1 cp data visible

        const int tcb = tbase + c * CHUNK;
#pragma unroll
        for (int i = 0; i < 4; i++) {
            int idx = i * 256 + tid;
            int pl = idx >> 9, rem = idx & 511;
            int r = rem >> 4, sg = rem & 15;
            uint4 v = *(const uint4*)(stg + pl * 4352 + r * 136 + sg * 8);
            *(uint4*)(actout + ((size_t)(n * 2 + pl) * T_LEN + tcb + r) * CH + sg * 8) = v;
        }
    }
}

// ---------------- classifier: 128 -> 256, + bias, no relu ----------------
// smem (u32): [0,17408) WC [pl][128][68]; [17408,26112) X [buf2][pl2][32][68];
//             [26112,30464) stage f32 [128][34]
__global__ void __launch_bounds__(256, 1) cls_mma(
    const unsigned short* __restrict__ actin,
    const uint32_t* __restrict__ wc,
    const float* __restrict__ bias,
    float* __restrict__ out) {
    extern __shared__ uint32_t sm[];
    const uint32_t sb = smem_u32(sm);
    const int tid = threadIdx.x;
    const int lane = tid & 31, wid = tid >> 5;
    const int g = lane >> 2, tq = lane & 3;
    const int n = blockIdx.y;
    const int tbase = blockIdx.x * SPAN;
    const int mz = blockIdx.z * 128;
    const int m0 = (wid & 3) * 32;
    const int n0 = (wid >> 2) * 16;

#pragma unroll
    for (int i = 0; i < 16; i++) {
        int idx = i * 256 + tid;
        int row = idx >> 4, seg = idx & 15;
        const uint32_t* src = wc + ((size_t)(row >> 7) * 256 + mz + (row & 127)) * 64 + seg * 4;
        cpa16(sb + (row * 68 + seg * 4) * 4, src, 16);
    }
    CP_COMMIT();

    auto load_x = [&](int c) {
        int buf = c & 1;
        int tcb = tbase + c * CHUNK;
#pragma unroll
        for (int i = 0; i < 4; i++) {
            int idx = i * 256 + tid;
            int pl = idx >> 9, rem = idx & 511;
            int r = rem >> 4, seg = rem & 15;
            const unsigned short* src =
                actin + ((size_t)(n * 2 + pl) * T_LEN + tcb + r) * CH + seg * 8;
            cpa16(sb + (17408 + buf * 4352 + pl * 2176 + r * 68 + seg * 4) * 4, src, 16);
        }
        CP_COMMIT();
    };
    load_x(0);
    load_x(1);
    CP_WAIT1();
    __syncthreads();

    float* stg = (float*)(sm + 26112);

#pragma unroll 1
    for (int c = 0; c < NCHUNK; c++) {
        const int buf = c & 1;
        const uint32_t* X = sm + 17408 + buf * 4352;

        float acc[2][2][4];
#pragma unroll
        for (int mt = 0; mt < 2; mt++)
#pragma unroll
            for (int nt = 0; nt < 2; nt++)
#pragma unroll
                for (int j = 0; j < 4; j++) acc[mt][nt][j] = 0.f;

#pragma unroll
        for (int pass = 0; pass < 3; pass++) {
            const int wp = (pass == 2) ? 1 : 0;
            const int xp = (pass == 1) ? 1 : 0;
            const uint32_t* Wt = sm + wp * 8704;
            const uint32_t* Xt = X + xp * 2176;
#pragma unroll
            for (int ks = 0; ks < 8; ks++) {
                uint32_t a[2][4], b0[2], b1[2];
#pragma unroll
                for (int mt = 0; mt < 2; mt++) {
                    a[mt][0] = Wt[(m0 + mt * 16 + g) * 68 + ks * 8 + tq];
                    a[mt][1] = Wt[(m0 + mt * 16 + g + 8) * 68 + ks * 8 + tq];
                    a[mt][2] = Wt[(m0 + mt * 16 + g) * 68 + ks * 8 + 4 + tq];
                    a[mt][3] = Wt[(m0 + mt * 16 + g + 8) * 68 + ks * 8 + 4 + tq];
                }
#pragma unroll
                for (int nt = 0; nt < 2; nt++) {
                    const uint32_t* xr = Xt + (n0 + nt * 8 + g) * 68;
                    b0[nt] = xr[ks * 8 + tq];
                    b1[nt] = xr[ks * 8 + 4 + tq];
                }
#pragma unroll
                for (int mt = 0; mt < 2; mt++)
#pragma unroll
                    for (int nt = 0; nt < 2; nt++)
                        mma16816(acc[mt][nt], a[mt], b0[nt], b1[nt]);
            }
        }

        __syncthreads();
        if (c + 2 < NCHUNK) load_x(c + 2);

#pragma unroll
        for (int mt = 0; mt < 2; mt++)
#pragma unroll
            for (int nt = 0; nt < 2; nt++)
#pragma unroll
                for (int ci = 0; ci < 4; ci++) {
                    int m = m0 + mt * 16 + g + ((ci >> 1) * 8);
                    int tl = n0 + nt * 8 + tq * 2 + (ci & 1);
                    stg[m * 34 + tl] = acc[mt][nt][ci] + __ldg(bias + mz + m);
                }

        if (c + 1 < NCHUNK) {
            if (c + 2 < NCHUNK) CP_WAIT1();
            else CP_WAIT0();
        }
        __syncthreads();

        const int tcb = tbase + c * CHUNK;
#pragma unroll
        for (int i = 0; i < 8; i++) {
            int idx = i * 256 + tid;
            int row = idx >> 4, sg = idx & 15;
            float2 v = *(const float2*)(stg + row * 34 + sg * 2);
            *(float2*)(out + ((size_t)n * NCLS + mz + row) * T_LEN + tcb + sg * 2) = v;
        }
    }
}

// ---------------- launch ----------------
extern "C" void kernel_launch(void* const* d_in, const int* in_sizes, int n_in,
                              void* d_out, int out_size) {
    (void)in_sizes; (void)n_in; (void)out_size;
    const float* seq     = (const float*)d_in[0];
    const float* w_first = (const float*)d_in[1];
    const float* w_rest  = (const float*)d_in[2];
    const float* w_cls   = (const float*)d_in[3];
    const float* b_cls   = (const float*)d_in[4];
    float* out = (float*)d_out;

    unsigned short *a0, *a1;
    uint32_t *whi, *wlo, *wc;
    cudaGetSymbolAddress((void**)&a0, g_act0);
    cudaGetSymbolAddress((void**)&a1, g_act1);
    cudaGetSymbolAddress((void**)&whi, g_whi);
    cudaGetSymbolAddress((void**)&wlo, g_wlo);
    cudaGetSymbolAddress((void**)&wc, g_wc);

    const int smem_layer = 56576 * 4;  // 226304 B
    const int smem_cls   = 30464 * 4;  // 121856 B
    cudaFuncSetAttribute(layer_mma, cudaFuncAttributeMaxDynamicSharedMemorySize, smem_layer);
    cudaFuncSetAttribute(cls_mma, cudaFuncAttributeMaxDynamicSharedMemorySize, smem_cls);

    prep_kernel<<<(27 * 2 * 128 * 64 + 255) / 256, 256>>>(w_rest, w_cls, whi, wlo, wc);
    layer0_kernel<<<dim3(T_LEN / 128, NB), 256>>>(seq, w_first, a0);

    for (int i = 1; i < 28; i++) {
        int l = i % 14;
        int d = 1 << (l % 10);
        const unsigned short* src = (i & 1) ? a0 : a1;
        unsigned short* dst       = (i & 1) ? a1 : a0;
        layer_mma<<<dim3(NXCTA, NB), 256, smem_layer>>>(
            src, dst, whi + (size_t)(i - 1) * 2 * 128 * 64,
            wlo + (size_t)(i - 1) * 2 * 128 * 64, d);
    }

    cls_mma<<<dim3(NXCTA, NB, 2), 256, smem_cls>>>(a1, wc, b_cls, out);
}

// round 8
// speedup vs baseline: 1.1647x; 1.0163x over previous
#include <cuda_runtime.h>
#include <cuda_bf16.h>
#include <cstdint>

#define T_LEN 64000
#define NB 4
#define CH 128
#define NCLS 256
#define CHUNK 32
#define NCHUNK 8
#define SPAN (CHUNK * NCHUNK)      // 256 t per CTA
#define NXCTA (T_LEN / SPAN)       // 250

// ---------------- static device buffers ----------------
__device__ unsigned short g_act0[(size_t)NB * 2 * T_LEN * CH];
__device__ unsigned short g_act1[(size_t)NB * 2 * T_LEN * CH];
__device__ uint32_t g_whi[27 * 2 * 128 * 64];
__device__ uint32_t g_wlo[27 * 2 * 128 * 64];
__device__ uint32_t g_wc[2 * 256 * 64];

// ---------------- helpers ----------------
__device__ __forceinline__ uint32_t smem_u32(const void* p) {
    uint32_t a;
    asm("{ .reg .u64 t; cvta.to.shared.u64 t, %1; cvt.u32.u64 %0, t; }" : "=r"(a) : "l"(p));
    return a;
}
__device__ __forceinline__ void cpa16(uint32_t dst, const void* src, int sz) {
    asm volatile("cp.async.cg.shared.global [%0], [%1], 16, %2;"
                 :: "r"(dst), "l"(src), "r"(sz) : "memory");
}
#define CP_COMMIT() asm volatile("cp.async.commit_group;" ::: "memory")
#define CP_WAIT1()  asm volatile("cp.async.wait_group 1;" ::: "memory")
#define CP_WAIT0()  asm volatile("cp.async.wait_group 0;" ::: "memory")

__device__ __forceinline__ void mma16816(float c[4], const uint32_t a[4],
                                         uint32_t b0, uint32_t b1) {
    asm volatile(
        "mma.sync.aligned.m16n8k16.row.col.f32.bf16.bf16.f32 "
        "{%0,%1,%2,%3}, {%4,%5,%6,%7}, {%8,%9}, {%0,%1,%2,%3};"
        : "+f"(c[0]), "+f"(c[1]), "+f"(c[2]), "+f"(c[3])
        : "r"(a[0]), "r"(a[1]), "r"(a[2]), "r"(a[3]), "r"(b0), "r"(b1));
}

// ---------------- prep: split + pack weights ----------------
__device__ __forceinline__ uint32_t pack_split(float w0, float w1, int plane) {
    __nv_bfloat16 h0 = __float2bfloat16(w0), h1 = __float2bfloat16(w1);
    if (plane == 0)
        return (uint32_t)__bfloat16_as_ushort(h0) |
               ((uint32_t)__bfloat16_as_ushort(h1) << 16);
    __nv_bfloat16 l0 = __float2bfloat16(w0 - __bfloat162float(h0));
    __nv_bfloat16 l1 = __float2bfloat16(w1 - __bfloat162float(h1));
    return (uint32_t)__bfloat16_as_ushort(l0) |
           ((uint32_t)__bfloat16_as_ushort(l1) << 16);
}

__global__ void prep_kernel(const float* __restrict__ wrest,
                            const float* __restrict__ wcls,
                            uint32_t* __restrict__ whi,
                            uint32_t* __restrict__ wlo,
                            uint32_t* __restrict__ wc) {
    int idx = blockIdx.x * blockDim.x + threadIdx.x;
    if (idx < 27 * 2 * 128 * 64) {
        int kp = idx & 63;
        int m = (idx >> 6) & 127;
        int tap = (idx >> 13) & 1;
        int L = idx >> 14;
        float w0 = wrest[((L * 128 + m) * 128 + kp * 2) * 2 + tap];
        float w1 = wrest[((L * 128 + m) * 128 + kp * 2 + 1) * 2 + tap];
        whi[idx] = pack_split(w0, w1, 0);
        wlo[idx] = pack_split(w0, w1, 1);
    }
    if (idx < 2 * 256 * 64) {
        int kp = idx & 63;
        int m = (idx >> 6) & 255;
        int pl = idx >> 14;
        float w0 = wcls[m * 128 + kp * 2];
        float w1 = wcls[m * 128 + kp * 2 + 1];
        wc[idx] = pack_split(w0, w1, pl);
    }
}

// ---------------- layer 0 ----------------
__global__ void layer0_kernel(const float* __restrict__ seq,
                              const float* __restrict__ wf,
                              unsigned short* __restrict__ actout) {
    int oc = threadIdx.x & 127;
    int half = threadIdx.x >> 7;
    int n = blockIdx.y;
    int t0 = blockIdx.x * 128 + half * 64;
    float w0 = wf[oc * 2], w1 = wf[oc * 2 + 1];
    const float* xs = seq + (size_t)n * T_LEN;
    unsigned short* ohi = actout + (size_t)(n * 2 + 0) * T_LEN * CH;
    unsigned short* olo = actout + (size_t)(n * 2 + 1) * T_LEN * CH;
    for (int j = 0; j < 64; j++) {
        int t = t0 + j;
        float x1 = xs[t];
        float x0 = (t >= 1) ? xs[t - 1] : 0.f;
        float y = fmaxf(w0 * x0 + w1 * x1, 0.f);
        __nv_bfloat16 h = __float2bfloat16(y);
        __nv_bfloat16 l = __float2bfloat16(y - __bfloat162float(h));
        ohi[(size_t)t * CH + oc] = __bfloat16_as_ushort(h);
        olo[(size_t)t * CH + oc] = __bfloat16_as_ushort(l);
    }
}

// ---------------- dilated-conv layer via mma.sync bf16 ----------------
// smem (u32 units):
//   [0, 34816)        W : [pl 2][tap 2][m 128][68]
//   [34816, 52224)    X : [buf 2][tile 4 = tap*2+plane][r 32][68]
//   [52224, 56576)    stage: u16[2 pl][32 t][136 m]
// CTA tile per chunk: 128 oc x 32 t. 8 warps = 4(m) x 2(n).
// Mainloop: per (tap, ks) load a_hi/a_lo/b_hi/b_lo ONCE, issue 3 products.
__global__ void __launch_bounds__(256, 1) layer_mma(
    const unsigned short* __restrict__ actin,
    unsigned short* __restrict__ actout,
    const uint32_t* __restrict__ whi,
    const uint32_t* __restrict__ wlo, int d) {
    extern __shared__ uint32_t sm[];
    const uint32_t sb = smem_u32(sm);
    const int tid = threadIdx.x;
    const int lane = tid & 31, wid = tid >> 5;
    const int g = lane >> 2, tq = lane & 3;
    const int n = blockIdx.y;
    const int tbase = blockIdx.x * SPAN;
    const int m0 = (wid & 3) * 32;
    const int n0 = (wid >> 2) * 16;

    // ---- group 0: W (both planes) -> smem
#pragma unroll
    for (int i = 0; i < 32; i++) {
        int idx = i * 256 + tid;         // 8192 segs of 16B
        int row = idx >> 4, seg = idx & 15;   // row = pl*256 + tap*128 + m
        const uint32_t* src = ((row < 256) ? whi : wlo) + (row & 255) * 64 + seg * 4;
        cpa16(sb + (row * 68 + seg * 4) * 4, src, 16);
    }
    CP_COMMIT();

    auto load_x = [&](int c) {
        int buf = c & 1;
        int tcb = tbase + c * CHUNK;
#pragma unroll
        for (int i = 0; i < 8; i++) {
            int idx = i * 256 + tid;
            int tile = idx >> 9, rem = idx & 511;
            int r = rem >> 4, seg = rem & 15;
            int tap = tile >> 1, pl = tile & 1;
            int t = tcb + r - (tap == 0 ? d : 0);
            const unsigned short* src =
                actin + ((size_t)(n * 2 + pl) * T_LEN + (t < 0 ? 0 : t)) * CH + seg * 8;
            cpa16(sb + (34816 + buf * 8704 + tile * 2176 + r * 68 + seg * 4) * 4,
                  src, t >= 0 ? 16 : 0);
        }
        CP_COMMIT();
    };
    load_x(0);
    load_x(1);

    CP_WAIT1();          // W + chunk0 complete (chunk1 in flight)
    __syncthreads();

    unsigned short* stg = (unsigned short*)(sm + 52224);

#pragma unroll 1
    for (int c = 0; c < NCHUNK; c++) {
        const int buf = c & 1;
        const uint32_t* X = sm + 34816 + buf * 8704;

        float acc[2][2][4];
#pragma unroll
        for (int mt = 0; mt < 2; mt++)
#pragma unroll
            for (int nt = 0; nt < 2; nt++)
#pragma unroll
                for (int j = 0; j < 4; j++) acc[mt][nt][j] = 0.f;

#pragma unroll
        for (int tap = 0; tap < 2; tap++) {
            const uint32_t* Wh = sm + tap * 8704;            // whi[tap]
            const uint32_t* Wl = sm + 17408 + tap * 8704;    // wlo[tap]
            const uint32_t* Xh = X + (tap * 2 + 0) * 2176;
            const uint32_t* Xl = X + (tap * 2 + 1) * 2176;
#pragma unroll
            for (int ks = 0; ks < 8; ks++) {
                uint32_t ah[2][4], al[2][4];
                uint32_t bh0[2], bh1[2], bl0[2], bl1[2];
#pragma unroll
                for (int mt = 0; mt < 2; mt++) {
                    int r0 = (m0 + mt * 16 + g) * 68, r1 = (m0 + mt * 16 + g + 8) * 68;
                    ah[mt][0] = Wh[r0 + ks * 8 + tq];
                    ah[mt][1] = Wh[r1 + ks * 8 + tq];
                    ah[mt][2] = Wh[r0 + ks * 8 + 4 + tq];
                    ah[mt][3] = Wh[r1 + ks * 8 + 4 + tq];
                    al[mt][0] = Wl[r0 + ks * 8 + tq];
                    al[mt][1] = Wl[r1 + ks * 8 + tq];
                    al[mt][2] = Wl[r0 + ks * 8 + 4 + tq];
                    al[mt][3] = Wl[r1 + ks * 8 + 4 + tq];
                }
#pragma unroll
                for (int nt = 0; nt < 2; nt++) {
                    int xr = (n0 + nt * 8 + g) * 68;
                    bh0[nt] = Xh[xr + ks * 8 + tq];
                    bh1[nt] = Xh[xr + ks * 8 + 4 + tq];
                    bl0[nt] = Xl[xr + ks * 8 + tq];
                    bl1[nt] = Xl[xr + ks * 8 + 4 + tq];
                }
#pragma unroll
                for (int mt = 0; mt < 2; mt++)
#pragma unroll
                    for (int nt = 0; nt < 2; nt++) {
                        mma16816(acc[mt][nt], ah[mt], bh0[nt], bh1[nt]);
                        mma16816(acc[mt][nt], ah[mt], bl0[nt], bl1[nt]);
                        mma16816(acc[mt][nt], al[mt], bh0[nt], bh1[nt]);
                    }
            }
        }

        __syncthreads();  // X[buf] reads done by all warps; stage(prev) reads done

        if (c + 2 < NCHUNK) load_x(c + 2);  // overlaps epilogue + next chunk MMA

        // -- epilogue: relu + split into dedicated stage
#pragma unroll
        for (int mt = 0; mt < 2; mt++)
#pragma unroll
            for (int nt = 0; nt < 2; nt++)
#pragma unroll
                for (int ci = 0; ci < 4; ci++) {
                    int m = m0 + mt * 16 + g + ((ci >> 1) * 8);
                    int tl = n0 + nt * 8 + tq * 2 + (ci & 1);
                    float y = fmaxf(acc[mt][nt][ci], 0.f);
                    __nv_bfloat16 h = __float2bfloat16(y);
                    __nv_bfloat16 l = __float2bfloat16(y - __bfloat162float(h));
                    stg[tl * 136 + m] = __bfloat16_as_ushort(h);
                    stg[4352 + tl * 136 + m] = __bfloat16_as_ushort(l);
                }

        if (c + 1 < NCHUNK) {
            if (c + 2 < NCHUNK) CP_WAIT1();
            else CP_WAIT0();
        }
        __syncthreads();  // stage visible + chunk c+1 cp data visible

        const int tcb = tbase + c * CHUNK;
#pragma unroll
        for (int i = 0; i < 4; i++) {
            int idx = i * 256 + tid;
            int pl = idx >> 9, rem = idx & 511;
            int r = rem >> 4, sg = rem & 15;
            uint4 v = *(const uint4*)(stg + pl * 4352 + r * 136 + sg * 8);
            *(uint4*)(actout + ((size_t)(n * 2 + pl) * T_LEN + tcb + r) * CH + sg * 8) = v;
        }
    }
}

// ---------------- classifier: 128 -> 256, + bias, no relu ----------------
// smem (u32): [0,17408) WC [pl][128][68]; [17408,26112) X [buf2][pl2][32][68];
//             [26112,30464) stage f32 [128][34]
__global__ void __launch_bounds__(256, 1) cls_mma(
    const unsigned short* __restrict__ actin,
    const uint32_t* __restrict__ wc,
    const float* __restrict__ bias,
    float* __restrict__ out) {
    extern __shared__ uint32_t sm[];
    const uint32_t sb = smem_u32(sm);
    const int tid = threadIdx.x;
    const int lane = tid & 31, wid = tid >> 5;
    const int g = lane >> 2, tq = lane & 3;
    const int n = blockIdx.y;
    const int tbase = blockIdx.x * SPAN;
    const int mz = blockIdx.z * 128;
    const int m0 = (wid & 3) * 32;
    const int n0 = (wid >> 2) * 16;

#pragma unroll
    for (int i = 0; i < 16; i++) {
        int idx = i * 256 + tid;
        int row = idx >> 4, seg = idx & 15;
        const uint32_t* src = wc + ((size_t)(row >> 7) * 256 + mz + (row & 127)) * 64 + seg * 4;
        cpa16(sb + (row * 68 + seg * 4) * 4, src, 16);
    }
    CP_COMMIT();

    auto load_x = [&](int c) {
        int buf = c & 1;
        int tcb = tbase + c * CHUNK;
#pragma unroll
        for (int i = 0; i < 4; i++) {
            int idx = i * 256 + tid;
            int pl = idx >> 9, rem = idx & 511;
            int r = rem >> 4, seg = rem & 15;
            const unsigned short* src =
                actin + ((size_t)(n * 2 + pl) * T_LEN + tcb + r) * CH + seg * 8;
            cpa16(sb + (17408 + buf * 4352 + pl * 2176 + r * 68 + seg * 4) * 4, src, 16);
        }
        CP_COMMIT();
    };
    load_x(0);
    load_x(1);
    CP_WAIT1();
    __syncthreads();

    float* stg = (float*)(sm + 26112);

#pragma unroll 1
    for (int c = 0; c < NCHUNK; c++) {
        const int buf = c & 1;
        const uint32_t* X = sm + 17408 + buf * 4352;

        float acc[2][2][4];
#pragma unroll
        for (int mt = 0; mt < 2; mt++)
#pragma unroll
            for (int nt = 0; nt < 2; nt++)
#pragma unroll
                for (int j = 0; j < 4; j++) acc[mt][nt][j] = 0.f;

        const uint32_t* Wh = sm;            // wc hi
        const uint32_t* Wl = sm + 8704;     // wc lo
        const uint32_t* Xh = X;
        const uint32_t* Xl = X + 2176;
#pragma unroll
        for (int ks = 0; ks < 8; ks++) {
            uint32_t ah[2][4], al[2][4];
            uint32_t bh0[2], bh1[2], bl0[2], bl1[2];
#pragma unroll
            for (int mt = 0; mt < 2; mt++) {
                int r0 = (m0 + mt * 16 + g) * 68, r1 = (m0 + mt * 16 + g + 8) * 68;
                ah[mt][0] = Wh[r0 + ks * 8 + tq];
                ah[mt][1] = Wh[r1 + ks * 8 + tq];
                ah[mt][2] = Wh[r0 + ks * 8 + 4 + tq];
                ah[mt][3] = Wh[r1 + ks * 8 + 4 + tq];
                al[mt][0] = Wl[r0 + ks * 8 + tq];
                al[mt][1] = Wl[r1 + ks * 8 + tq];
                al[mt][2] = Wl[r0 + ks * 8 + 4 + tq];
                al[mt][3] = Wl[r1 + ks * 8 + 4 + tq];
            }
#pragma unroll
            for (int nt = 0; nt < 2; nt++) {
                int xr = (n0 + nt * 8 + g) * 68;
                bh0[nt] = Xh[xr + ks * 8 + tq];
                bh1[nt] = Xh[xr + ks * 8 + 4 + tq];
                bl0[nt] = Xl[xr + ks * 8 + tq];
                bl1[nt] = Xl[xr + ks * 8 + 4 + tq];
            }
#pragma unroll
            for (int mt = 0; mt < 2; mt++)
#pragma unroll
                for (int nt = 0; nt < 2; nt++) {
                    mma16816(acc[mt][nt], ah[mt], bh0[nt], bh1[nt]);
                    mma16816(acc[mt][nt], ah[mt], bl0[nt], bl1[nt]);
                    mma16816(acc[mt][nt], al[mt], bh0[nt], bh1[nt]);
                }
        }

        __syncthreads();
        if (c + 2 < NCHUNK) load_x(c + 2);

#pragma unroll
        for (int mt = 0; mt < 2; mt++)
#pragma unroll
            for (int nt = 0; nt < 2; nt++)
#pragma unroll
                for (int ci = 0; ci < 4; ci++) {
                    int m = m0 + mt * 16 + g + ((ci >> 1) * 8);
                    int tl = n0 + nt * 8 + tq * 2 + (ci & 1);
                    stg[m * 34 + tl] = acc[mt][nt][ci] + __ldg(bias + mz + m);
                }

        if (c + 1 < NCHUNK) {
            if (c + 2 < NCHUNK) CP_WAIT1();
            else CP_WAIT0();
        }
        __syncthreads();

        const int tcb = tbase + c * CHUNK;
#pragma unroll
        for (int i = 0; i < 8; i++) {
            int idx = i * 256 + tid;
            int row = idx >> 4, sg = idx & 15;
            float2 v = *(const float2*)(stg + row * 34 + sg * 2);
            *(float2*)(out + ((size_t)n * NCLS + mz + row) * T_LEN + tcb + sg * 2) = v;
        }
    }
}

// ---------------- launch ----------------
extern "C" void kernel_launch(void* const* d_in, const int* in_sizes, int n_in,
                              void* d_out, int out_size) {
    (void)in_sizes; (void)n_in; (void)out_size;
    const float* seq     = (const float*)d_in[0];
    const float* w_first = (const float*)d_in[1];
    const float* w_rest  = (const float*)d_in[2];
    const float* w_cls   = (const float*)d_in[3];
    const float* b_cls   = (const float*)d_in[4];
    float* out = (float*)d_out;

    unsigned short *a0, *a1;
    uint32_t *whi, *wlo, *wc;
    cudaGetSymbolAddress((void**)&a0, g_act0);
    cudaGetSymbolAddress((void**)&a1, g_act1);
    cudaGetSymbolAddress((void**)&whi, g_whi);
    cudaGetSymbolAddress((void**)&wlo, g_wlo);
    cudaGetSymbolAddress((void**)&wc, g_wc);

    const int smem_layer = 56576 * 4;  // 226304 B
    const int smem_cls   = 30464 * 4;  // 121856 B
    cudaFuncSetAttribute(layer_mma, cudaFuncAttributeMaxDynamicSharedMemorySize, smem_layer);
    cudaFuncSetAttribute(cls_mma, cudaFuncAttributeMaxDynamicSharedMemorySize, smem_cls);

    prep_kernel<<<(27 * 2 * 128 * 64 + 255) / 256, 256>>>(w_rest, w_cls, whi, wlo, wc);
    layer0_kernel<<<dim3(T_LEN / 128, NB), 256>>>(seq, w_first, a0);

    for (int i = 1; i < 28; i++) {
        int l = i % 14;
        int d = 1 << (l % 10);
        const unsigned short* src = (i & 1) ? a0 : a1;
        unsigned short* dst       = (i & 1) ? a1 : a0;
        layer_mma<<<dim3(NXCTA, NB), 256, smem_layer>>>(
            src, dst, whi + (size_t)(i - 1) * 2 * 128 * 64,
            wlo + (size_t)(i - 1) * 2 * 128 * 64, d);
    }

    cls_mma<<<dim3(NXCTA, NB, 2), 256, smem_cls>>>(a1, wc, b_cls, out);
}

// round 9
// speedup vs baseline: 1.1825x; 1.0153x over previous
#include <cuda_runtime.h>
#include <cuda_bf16.h>
#include <cstdint>

#define T_LEN 64000
#define NB 4
#define CH 128
#define NCLS 256
#define CHUNK 32
#define NCHUNK 8
#define SPAN (CHUNK * NCHUNK)      // 256 t per CTA
#define NXCTA (T_LEN / SPAN)       // 250

// ---------------- static device buffers ----------------
__device__ unsigned short g_act0[(size_t)NB * 2 * T_LEN * CH];
__device__ unsigned short g_act1[(size_t)NB * 2 * T_LEN * CH];
__device__ uint32_t g_whi[27 * 2 * 128 * 64];
__device__ uint32_t g_wlo[27 * 2 * 128 * 64];
__device__ uint32_t g_wc[2 * 256 * 64];

// ---------------- helpers ----------------
__device__ __forceinline__ uint32_t smem_u32(const void* p) {
    uint32_t a;
    asm("{ .reg .u64 t; cvta.to.shared.u64 t, %1; cvt.u32.u64 %0, t; }" : "=r"(a) : "l"(p));
    return a;
}
__device__ __forceinline__ void cpa16(uint32_t dst, const void* src, int sz) {
    asm volatile("cp.async.cg.shared.global [%0], [%1], 16, %2;"
                 :: "r"(dst), "l"(src), "r"(sz) : "memory");
}
#define CP_COMMIT() asm volatile("cp.async.commit_group;" ::: "memory")
#define CP_WAIT1()  asm volatile("cp.async.wait_group 1;" ::: "memory")
#define CP_WAIT0()  asm volatile("cp.async.wait_group 0;" ::: "memory")

__device__ __forceinline__ void mma16816(float c[4], const uint32_t a[4],
                                         uint32_t b0, uint32_t b1) {
    asm volatile(
        "mma.sync.aligned.m16n8k16.row.col.f32.bf16.bf16.f32 "
        "{%0,%1,%2,%3}, {%4,%5,%6,%7}, {%8,%9}, {%0,%1,%2,%3};"
        : "+f"(c[0]), "+f"(c[1]), "+f"(c[2]), "+f"(c[3])
        : "r"(a[0]), "r"(a[1]), "r"(a[2]), "r"(a[3]), "r"(b0), "r"(b1));
}

// ---------------- prep: split + pack weights ----------------
__device__ __forceinline__ uint32_t pack_split(float w0, float w1, int plane) {
    __nv_bfloat16 h0 = __float2bfloat16(w0), h1 = __float2bfloat16(w1);
    if (plane == 0)
        return (uint32_t)__bfloat16_as_ushort(h0) |
               ((uint32_t)__bfloat16_as_ushort(h1) << 16);
    __nv_bfloat16 l0 = __float2bfloat16(w0 - __bfloat162float(h0));
    __nv_bfloat16 l1 = __float2bfloat16(w1 - __bfloat162float(h1));
    return (uint32_t)__bfloat16_as_ushort(l0) |
           ((uint32_t)__bfloat16_as_ushort(l1) << 16);
}

__global__ void prep_kernel(const float* __restrict__ wrest,
                            const float* __restrict__ wcls,
                            uint32_t* __restrict__ whi,
                            uint32_t* __restrict__ wlo,
                            uint32_t* __restrict__ wc) {
    int idx = blockIdx.x * blockDim.x + threadIdx.x;
    if (idx < 27 * 2 * 128 * 64) {
        int kp = idx & 63;
        int m = (idx >> 6) & 127;
        int tap = (idx >> 13) & 1;
        int L = idx >> 14;
        float w0 = wrest[((L * 128 + m) * 128 + kp * 2) * 2 + tap];
        float w1 = wrest[((L * 128 + m) * 128 + kp * 2 + 1) * 2 + tap];
        whi[idx] = pack_split(w0, w1, 0);
        wlo[idx] = pack_split(w0, w1, 1);
    }
    if (idx < 2 * 256 * 64) {
        int kp = idx & 63;
        int m = (idx >> 6) & 255;
        int pl = idx >> 14;
        float w0 = wcls[m * 128 + kp * 2];
        float w1 = wcls[m * 128 + kp * 2 + 1];
        wc[idx] = pack_split(w0, w1, pl);
    }
}

// ---------------- layer 0 ----------------
__global__ void layer0_kernel(const float* __restrict__ seq,
                              const float* __restrict__ wf,
                              unsigned short* __restrict__ actout) {
    int oc = threadIdx.x & 127;
    int half = threadIdx.x >> 7;
    int n = blockIdx.y;
    int t0 = blockIdx.x * 128 + half * 64;
    float w0 = wf[oc * 2], w1 = wf[oc * 2 + 1];
    const float* xs = seq + (size_t)n * T_LEN;
    unsigned short* ohi = actout + (size_t)(n * 2 + 0) * T_LEN * CH;
    unsigned short* olo = actout + (size_t)(n * 2 + 1) * T_LEN * CH;
    for (int j = 0; j < 64; j++) {
        int t = t0 + j;
        float x1 = xs[t];
        float x0 = (t >= 1) ? xs[t - 1] : 0.f;
        float y = fmaxf(w0 * x0 + w1 * x1, 0.f);
        __nv_bfloat16 h = __float2bfloat16(y);
        __nv_bfloat16 l = __float2bfloat16(y - __bfloat162float(h));
        ohi[(size_t)t * CH + oc] = __bfloat16_as_ushort(h);
        olo[(size_t)t * CH + oc] = __bfloat16_as_ushort(l);
    }
}

// ---------------- dilated-conv layer via mma.sync bf16 ----------------
// smem (u32 units):
//   [0, 34816)        W : [pl 2][tap 2][m 128][68]
//   [34816, 52224)    X : [buf 2][tile 4 = tap*2+plane][r 32][68]
//   [52224, 56576)    stage: u16[2 pl][32 t][136 m]
// 3 independent accumulator sets (hh, hl, lh) -> no per-ks HMMA chains.
__global__ void __launch_bounds__(256, 1) layer_mma(
    const unsigned short* __restrict__ actin,
    unsigned short* __restrict__ actout,
    const uint32_t* __restrict__ whi,
    const uint32_t* __restrict__ wlo, int d) {
    extern __shared__ uint32_t sm[];
    const uint32_t sb = smem_u32(sm);
    const int tid = threadIdx.x;
    const int lane = tid & 31, wid = tid >> 5;
    const int g = lane >> 2, tq = lane & 3;
    const int n = blockIdx.y;
    const int tbase = blockIdx.x * SPAN;
    const int m0 = (wid & 3) * 32;
    const int n0 = (wid >> 2) * 16;

    // ---- group 0: W (both planes) -> smem
#pragma unroll
    for (int i = 0; i < 32; i++) {
        int idx = i * 256 + tid;
        int row = idx >> 4, seg = idx & 15;   // row = pl*256 + tap*128 + m
        const uint32_t* src = ((row < 256) ? whi : wlo) + (row & 255) * 64 + seg * 4;
        cpa16(sb + (row * 68 + seg * 4) * 4, src, 16);
    }
    CP_COMMIT();

    auto load_x = [&](int c) {
        int buf = c & 1;
        int tcb = tbase + c * CHUNK;
#pragma unroll
        for (int i = 0; i < 8; i++) {
            int idx = i * 256 + tid;
            int tile = idx >> 9, rem = idx & 511;
            int r = rem >> 4, seg = rem & 15;
            int tap = tile >> 1, pl = tile & 1;
            int t = tcb + r - (tap == 0 ? d : 0);
            const unsigned short* src =
                actin + ((size_t)(n * 2 + pl) * T_LEN + (t < 0 ? 0 : t)) * CH + seg * 8;
            cpa16(sb + (34816 + buf * 8704 + tile * 2176 + r * 68 + seg * 4) * 4,
                  src, t >= 0 ? 16 : 0);
        }
        CP_COMMIT();
    };
    load_x(0);
    load_x(1);

    CP_WAIT1();
    __syncthreads();

    unsigned short* stg = (unsigned short*)(sm + 52224);

#pragma unroll 1
    for (int c = 0; c < NCHUNK; c++) {
        const int buf = c & 1;
        const uint32_t* X = sm + 34816 + buf * 8704;

        float acc[3][2][2][4];   // [product hh/hl/lh][mt][nt][ci]
#pragma unroll
        for (int p = 0; p < 3; p++)
#pragma unroll
            for (int mt = 0; mt < 2; mt++)
#pragma unroll
                for (int nt = 0; nt < 2; nt++)
#pragma unroll
                    for (int j = 0; j < 4; j++) acc[p][mt][nt][j] = 0.f;

#pragma unroll
        for (int tap = 0; tap < 2; tap++) {
            const uint32_t* Wh = sm + tap * 8704;
            const uint32_t* Wl = sm + 17408 + tap * 8704;
            const uint32_t* Xh = X + (tap * 2 + 0) * 2176;
            const uint32_t* Xl = X + (tap * 2 + 1) * 2176;
#pragma unroll
            for (int ks = 0; ks < 8; ks++) {
                uint32_t ah[2][4], al[2][4];
                uint32_t bh0[2], bh1[2], bl0[2], bl1[2];
#pragma unroll
                for (int mt = 0; mt < 2; mt++) {
                    int r0 = (m0 + mt * 16 + g) * 68, r1 = (m0 + mt * 16 + g + 8) * 68;
                    ah[mt][0] = Wh[r0 + ks * 8 + tq];
                    ah[mt][1] = Wh[r1 + ks * 8 + tq];
                    ah[mt][2] = Wh[r0 + ks * 8 + 4 + tq];
                    ah[mt][3] = Wh[r1 + ks * 8 + 4 + tq];
                    al[mt][0] = Wl[r0 + ks * 8 + tq];
                    al[mt][1] = Wl[r1 + ks * 8 + tq];
                    al[mt][2] = Wl[r0 + ks * 8 + 4 + tq];
                    al[mt][3] = Wl[r1 + ks * 8 + 4 + tq];
                }
#pragma unroll
                for (int nt = 0; nt < 2; nt++) {
                    int xr = (n0 + nt * 8 + g) * 68;
                    bh0[nt] = Xh[xr + ks * 8 + tq];
                    bh1[nt] = Xh[xr + ks * 8 + 4 + tq];
                    bl0[nt] = Xl[xr + ks * 8 + tq];
                    bl1[nt] = Xl[xr + ks * 8 + 4 + tq];
                }
                // 12 independent MMAs: distinct accumulators per product
#pragma unroll
                for (int mt = 0; mt < 2; mt++)
#pragma unroll
                    for (int nt = 0; nt < 2; nt++)
                        mma16816(acc[0][mt][nt], ah[mt], bh0[nt], bh1[nt]);
#pragma unroll
                for (int mt = 0; mt < 2; mt++)
#pragma unroll
                    for (int nt = 0; nt < 2; nt++)
                        mma16816(acc[1][mt][nt], ah[mt], bl0[nt], bl1[nt]);
#pragma unroll
                for (int mt = 0; mt < 2; mt++)
#pragma unroll
                    for (int nt = 0; nt < 2; nt++)
                        mma16816(acc[2][mt][nt], al[mt], bh0[nt], bh1[nt]);
            }
        }

        __syncthreads();

        if (c + 2 < NCHUNK) load_x(c + 2);

        // -- epilogue: sum partials, relu + split into dedicated stage
#pragma unroll
        for (int mt = 0; mt < 2; mt++)
#pragma unroll
            for (int nt = 0; nt < 2; nt++)
#pragma unroll
                for (int ci = 0; ci < 4; ci++) {
                    int m = m0 + mt * 16 + g + ((ci >> 1) * 8);
                    int tl = n0 + nt * 8 + tq * 2 + (ci & 1);
                    float y = acc[0][mt][nt][ci] + acc[1][mt][nt][ci] + acc[2][mt][nt][ci];
                    y = fmaxf(y, 0.f);
                    __nv_bfloat16 h = __float2bfloat16(y);
                    __nv_bfloat16 l = __float2bfloat16(y - __bfloat162float(h));
                    stg[tl * 136 + m] = __bfloat16_as_ushort(h);
                    stg[4352 + tl * 136 + m] = __bfloat16_as_ushort(l);
                }

        if (c + 1 < NCHUNK) {
            if (c + 2 < NCHUNK) CP_WAIT1();
            else CP_WAIT0();
        }
        __syncthreads();

        const int tcb = tbase + c * CHUNK;
#pragma unroll
        for (int i = 0; i < 4; i++) {
            int idx = i * 256 + tid;
            int pl = idx >> 9, rem = idx & 511;
            int r = rem >> 4, sg = rem & 15;
            uint4 v = *(const uint4*)(stg + pl * 4352 + r * 136 + sg * 8);
            *(uint4*)(actout + ((size_t)(n * 2 + pl) * T_LEN + tcb + r) * CH + sg * 8) = v;
        }
    }
}

// ---------------- classifier: 128 -> 256, + bias, no relu ----------------
__global__ void __launch_bounds__(256, 1) cls_mma(
    const unsigned short* __restrict__ actin,
    const uint32_t* __restrict__ wc,
    const float* __restrict__ bias,
    float* __restrict__ out) {
    extern __shared__ uint32_t sm[];
    const uint32_t sb = smem_u32(sm);
    const int tid = threadIdx.x;
    const int lane = tid & 31, wid = tid >> 5;
    const int g = lane >> 2, tq = lane & 3;
    const int n = blockIdx.y;
    const int tbase = blockIdx.x * SPAN;
    const int mz = blockIdx.z * 128;
    const int m0 = (wid & 3) * 32;
    const int n0 = (wid >> 2) * 16;

#pragma unroll
    for (int i = 0; i < 16; i++) {
        int idx = i * 256 + tid;
        int row = idx >> 4, seg = idx & 15;
        const uint32_t* src = wc + ((size_t)(row >> 7) * 256 + mz + (row & 127)) * 64 + seg * 4;
        cpa16(sb + (row * 68 + seg * 4) * 4, src, 16);
    }
    CP_COMMIT();

    auto load_x = [&](int c) {
        int buf = c & 1;
        int tcb = tbase + c * CHUNK;
#pragma unroll
        for (int i = 0; i < 4; i++) {
            int idx = i * 256 + tid;
            int pl = idx >> 9, rem = idx & 511;
            int r = rem >> 4, seg = rem & 15;
            const unsigned short* src =
                actin + ((size_t)(n * 2 + pl) * T_LEN + tcb + r) * CH + seg * 8;
            cpa16(sb + (17408 + buf * 4352 + pl * 2176 + r * 68 + seg * 4) * 4, src, 16);
        }
        CP_COMMIT();
    };
    load_x(0);
    load_x(1);
    CP_WAIT1();
    __syncthreads();

    float* stg = (float*)(sm + 26112);

#pragma unroll 1
    for (int c = 0; c < NCHUNK; c++) {
        const int buf = c & 1;
        const uint32_t* X = sm + 17408 + buf * 4352;

        float acc[3][2][2][4];
#pragma unroll
        for (int p = 0; p < 3; p++)
#pragma unroll
            for (int mt = 0; mt < 2; mt++)
#pragma unroll
                for (int nt = 0; nt < 2; nt++)
#pragma unroll
                    for (int j = 0; j < 4; j++) acc[p][mt][nt][j] = 0.f;

        const uint32_t* Wh = sm;
        const uint32_t* Wl = sm + 8704;
        const uint32_t* Xh = X;
        const uint32_t* Xl = X + 2176;
#pragma unroll
        for (int ks = 0; ks < 8; ks++) {
            uint32_t ah[2][4], al[2][4];
            uint32_t bh0[2], bh1[2], bl0[2], bl1[2];
#pragma unroll
            for (int mt = 0; mt < 2; mt++) {
                int r0 = (m0 + mt * 16 + g) * 68, r1 = (m0 + mt * 16 + g + 8) * 68;
                ah[mt][0] = Wh[r0 + ks * 8 + tq];
                ah[mt][1] = Wh[r1 + ks * 8 + tq];
                ah[mt][2] = Wh[r0 + ks * 8 + 4 + tq];
                ah[mt][3] = Wh[r1 + ks * 8 + 4 + tq];
                al[mt][0] = Wl[r0 + ks * 8 + tq];
                al[mt][1] = Wl[r1 + ks * 8 + tq];
                al[mt][2] = Wl[r0 + ks * 8 + 4 + tq];
                al[mt][3] = Wl[r1 + ks * 8 + 4 + tq];
            }
#pragma unroll
            for (int nt = 0; nt < 2; nt++) {
                int xr = (n0 + nt * 8 + g) * 68;
                bh0[nt] = Xh[xr + ks * 8 + tq];
                bh1[nt] = Xh[xr + ks * 8 + 4 + tq];
                bl0[nt] = Xl[xr + ks * 8 + tq];
                bl1[nt] = Xl[xr + ks * 8 + 4 + tq];
            }
#pragma unroll
            for (int mt = 0; mt < 2; mt++)
#pragma unroll
                for (int nt = 0; nt < 2; nt++)
                    mma16816(acc[0][mt][nt], ah[mt], bh0[nt], bh1[nt]);
#pragma unroll
            for (int mt = 0; mt < 2; mt++)
#pragma unroll
                for (int nt = 0; nt < 2; nt++)
                    mma16816(acc[1][mt][nt], ah[mt], bl0[nt], bl1[nt]);
#pragma unroll
            for (int mt = 0; mt < 2; mt++)
#pragma unroll
                for (int nt = 0; nt < 2; nt++)
                    mma16816(acc[2][mt][nt], al[mt], bh0[nt], bh1[nt]);
        }

        __syncthreads();
        if (c + 2 < NCHUNK) load_x(c + 2);

#pragma unroll
        for (int mt = 0; mt < 2; mt++)
#pragma unroll
            for (int nt = 0; nt < 2; nt++)
#pragma unroll
                for (int ci = 0; ci < 4; ci++) {
                    int m = m0 + mt * 16 + g + ((ci >> 1) * 8);
                    int tl = n0 + nt * 8 + tq * 2 + (ci & 1);
                    float y = acc[0][mt][nt][ci] + acc[1][mt][nt][ci] + acc[2][mt][nt][ci];
                    stg[m * 34 + tl] = y + __ldg(bias + mz + m);
                }

        if (c + 1 < NCHUNK) {
            if (c + 2 < NCHUNK) CP_WAIT1();
            else CP_WAIT0();
        }
        __syncthreads();

        const int tcb = tbase + c * CHUNK;
#pragma unroll
        for (int i = 0; i < 8; i++) {
            int idx = i * 256 + tid;
            int row = idx >> 4, sg = idx & 15;
            float2 v = *(const float2*)(stg + row * 34 + sg * 2);
            *(float2*)(out + ((size_t)n * NCLS + mz + row) * T_LEN + tcb + sg * 2) = v;
        }
    }
}

// ---------------- launch ----------------
extern "C" void kernel_launch(void* const* d_in, const int* in_sizes, int n_in,
                              void* d_out, int out_size) {
    (void)in_sizes; (void)n_in; (void)out_size;
    const float* seq     = (const float*)d_in[0];
    const float* w_first = (const float*)d_in[1];
    const float* w_rest  = (const float*)d_in[2];
    const float* w_cls   = (const float*)d_in[3];
    const float* b_cls   = (const float*)d_in[4];
    float* out = (float*)d_out;

    unsigned short *a0, *a1;
    uint32_t *whi, *wlo, *wc;
    cudaGetSymbolAddress((void**)&a0, g_act0);
    cudaGetSymbolAddress((void**)&a1, g_act1);
    cudaGetSymbolAddress((void**)&whi, g_whi);
    cudaGetSymbolAddress((void**)&wlo, g_wlo);
    cudaGetSymbolAddress((void**)&wc, g_wc);

    const int smem_layer = 56576 * 4;  // 226304 B
    const int smem_cls   = 30464 * 4;  // 121856 B
    cudaFuncSetAttribute(layer_mma, cudaFuncAttributeMaxDynamicSharedMemorySize, smem_layer);
    cudaFuncSetAttribute(cls_mma, cudaFuncAttributeMaxDynamicSharedMemorySize, smem_cls);

    prep_kernel<<<(27 * 2 * 128 * 64 + 255) / 256, 256>>>(w_rest, w_cls, whi, wlo, wc);
    layer0_kernel<<<dim3(T_LEN / 128, NB), 256>>>(seq, w_first, a0);

    for (int i = 1; i < 28; i++) {
        int l = i % 14;
        int d = 1 << (l % 10);
        const unsigned short* src = (i & 1) ? a0 : a1;
        unsigned short* dst       = (i & 1) ? a1 : a0;
        layer_mma<<<dim3(NXCTA, NB), 256, smem_layer>>>(
            src, dst, whi + (size_t)(i - 1) * 2 * 128 * 64,
            wlo + (size_t)(i - 1) * 2 * 128 * 64, d);
    }

    cls_mma<<<dim3(NXCTA, NB, 2), 256, smem_cls>>>(a1, wc, b_cls, out);
}